// round 6
// baseline (speedup 1.0000x reference)
#include <cuda_runtime.h>
#include <math.h>

#define BB 64
#define SS 1024
#define DD 1024
#define EE 8
#define KTOP 2

// wk_b geometry: warp = 4 token-octets, 2 tokens/lane, 8 tokens/warp
#define BTHREADS 256
#define WARPS_B (BTHREADS / 32)                // 8
#define TOK_PER_WARP 8
#define BLK_TOK (WARPS_B * TOK_PER_WARP)       // 64
#define NBLOCKS_B (BB * SS / BLK_TOK)          // 1024
#define BLOCKS_PER_BATCH (SS / BLK_TOK)        // 16

#define MASK_ELEMS (BB * SS * EE)   // 524288
#define IDX_OFF    MASK_ELEMS
#define LOSS_OFF   (MASK_ELEMS + BB * KTOP)

// ---------------- scratch (device globals: no allocation allowed) ----------
__device__ float g_W2[EE * DD];              // 32 KB
__device__ float g_b2[EE];
__device__ float g_pScores[NBLOCKS_B][EE];   // per-block partial softmax sums
__device__ float g_pAux[NBLOCKS_B];          // per-block partial aux sums
__device__ float g_mask2d[BB * EE];
__device__ unsigned int g_sync;              // last-block counter (self-resetting)

// ------------- Kernel W: W2 = key_emb @ Wq  and  b2 = key_emb @ bq ---------
// grid (E=8, dchunk=8), 256 thr. Warp og covers o in [og*128,(og+1)*128);
// lane owns 4 contiguous d. 8 e-blocks share each Wq chunk via L2.
__global__ void __launch_bounds__(256) wk_w(const float* __restrict__ Wq,
                                            const float* __restrict__ bq,
                                            const float* __restrict__ key) {
    __shared__ float4 s_red[8][32];
    __shared__ float  s_b2r[8];
    const int e = blockIdx.x, dc = blockIdx.y;
    const int tid = threadIdx.x, og = tid >> 5, lane = tid & 31;
    const int d = dc * 128 + lane * 4;
    const float* ke = key + e * DD;

    float4 acc = make_float4(0.f, 0.f, 0.f, 0.f);
    const float* wq = Wq + (size_t)(og * 128) * DD + d;
    #pragma unroll 4
    for (int o = 0; o < 128; o++) {
        float k  = __ldg(ke + og * 128 + o);
        float4 w = *(const float4*)(wq + (size_t)o * DD);
        acc.x = fmaf(k, w.x, acc.x); acc.y = fmaf(k, w.y, acc.y);
        acc.z = fmaf(k, w.z, acc.z); acc.w = fmaf(k, w.w, acc.w);
    }
    s_red[og][lane] = acc;

    float p = 0.f;
    if (dc == 0) {
        #pragma unroll
        for (int i = 0; i < 4; i++)
            p += bq[tid + i * 256] * __ldg(ke + tid + i * 256);
    }
    #pragma unroll
    for (int off = 16; off > 0; off >>= 1) p += __shfl_xor_sync(0xFFFFFFFFu, p, off);
    if (lane == 0) s_b2r[og] = p;
    __syncthreads();

    if (og == 0) {
        float4 s = s_red[0][lane];
        #pragma unroll
        for (int r = 1; r < 8; r++) {
            float4 q = s_red[r][lane];
            s.x += q.x; s.y += q.y; s.z += q.z; s.w += q.w;
        }
        *(float4*)&g_W2[e * DD + d] = s;
    }
    if (tid == 0 && dc == 0) {
        float b2 = 0.f;
        #pragma unroll
        for (int i = 0; i < 8; i++) b2 += s_b2r[i];
        g_b2[e] = b2;
    }
}

// ---------------- Kernel B: fused main pass + last-block finalize -----------
__global__ void __launch_bounds__(BTHREADS, 5) wk_b(const float* __restrict__ x,
                                                    float* __restrict__ out) {
    __shared__ float4 s_w2[EE * 256];            // 32 KB, [e][j]
    __shared__ float  s_b2[EE];
    __shared__ float  s_red[WARPS_B][EE];
    __shared__ float  s_aux[WARPS_B];
    __shared__ unsigned int s_last;

    const int tid = threadIdx.x;
    const float4* w2g = (const float4*)g_W2;
    #pragma unroll
    for (int i = 0; i < 8; i++) s_w2[tid + i * 256] = w2g[tid + i * 256];
    if (tid < EE) s_b2[tid] = g_b2[tid];
    __syncthreads();

    const int warp = tid >> 5, lane = tid & 31;
    const int oct  = lane >> 3;
    const int c    = lane & 7;
    const int tokBase = blockIdx.x * BLK_TOK + warp * TOK_PER_WARP;

    const float4* xg = (const float4*)x;
    const size_t base0 = (size_t)(tokBase + oct)     * 256 + c;
    const size_t base1 = (size_t)(tokBase + 4 + oct) * 256 + c;

    float acc[2][EE];
    #pragma unroll
    for (int t = 0; t < 2; t++)
        #pragma unroll
        for (int e = 0; e < EE; e++) acc[t][e] = 0.f;

    #pragma unroll 4
    for (int i = 0; i < 32; i++) {
        float4 xv0 = xg[base0 + i * 8];
        float4 xv1 = xg[base1 + i * 8];
        #pragma unroll
        for (int e = 0; e < EE; e++) {
            float4 wv = s_w2[e * 256 + i * 8 + c];
            acc[0][e] = fmaf(xv0.x, wv.x, acc[0][e]);
            acc[0][e] = fmaf(xv0.y, wv.y, acc[0][e]);
            acc[0][e] = fmaf(xv0.z, wv.z, acc[0][e]);
            acc[0][e] = fmaf(xv0.w, wv.w, acc[0][e]);
            acc[1][e] = fmaf(xv1.x, wv.x, acc[1][e]);
            acc[1][e] = fmaf(xv1.y, wv.y, acc[1][e]);
            acc[1][e] = fmaf(xv1.z, wv.z, acc[1][e]);
            acc[1][e] = fmaf(xv1.w, wv.w, acc[1][e]);
        }
    }

    // octet reduce
    #pragma unroll
    for (int t = 0; t < 2; t++)
        #pragma unroll
        for (int e = 0; e < EE; e++) {
            float v = acc[t][e];
            v += __shfl_xor_sync(0xFFFFFFFFu, v, 4);
            v += __shfl_xor_sync(0xFFFFFFFFu, v, 2);
            v += __shfl_xor_sync(0xFFFFFFFFu, v, 1);
            acc[t][e] = v;
        }

    // per-token softmax (redundant across octet lanes; only c==0 contributes)
    const float scale = 0.03125f;
    float b2r[EE];
    #pragma unroll
    for (int e = 0; e < EE; e++) b2r[e] = s_b2[e];

    float scoreAcc[EE];
    #pragma unroll
    for (int e = 0; e < EE; e++) scoreAcc[e] = 0.f;
    float auxAcc = 0.f;
    const float contrib = (c == 0) ? 1.0f : 0.0f;

    #pragma unroll
    for (int t = 0; t < 2; t++) {
        float z[EE];
        float m = -3.402823466e38f;
        #pragma unroll
        for (int e = 0; e < EE; e++) { z[e] = acc[t][e] + b2r[e]; m = fmaxf(m, z[e]); }
        float ex[EE];
        float denom = 0.f;
        #pragma unroll
        for (int e = 0; e < EE; e++) { ex[e] = __expf((z[e] - m) * scale); denom += ex[e]; }
        float rdenom = __frcp_rn(denom);
        #pragma unroll
        for (int e = 0; e < EE; e++) {
            float w = ex[e] * rdenom;
            scoreAcc[e] += contrib * w;
            auxAcc      += contrib * w * __logf(w + 1e-9f);
        }
    }

    // block reduce
    #pragma unroll
    for (int e = 0; e < EE; e++) {
        float v = scoreAcc[e];
        v += __shfl_xor_sync(0xFFFFFFFFu, v, 16);
        v += __shfl_xor_sync(0xFFFFFFFFu, v, 8);
        v += __shfl_xor_sync(0xFFFFFFFFu, v, 4);
        v += __shfl_xor_sync(0xFFFFFFFFu, v, 2);
        v += __shfl_xor_sync(0xFFFFFFFFu, v, 1);
        if (lane == 0) s_red[warp][e] = v;
    }
    float a = auxAcc;
    #pragma unroll
    for (int off = 16; off > 0; off >>= 1) a += __shfl_xor_sync(0xFFFFFFFFu, a, off);
    if (lane == 0) s_aux[warp] = a;
    __syncthreads();

    if (warp == 0) {
        if (lane < EE) {
            float s = 0.f;
            #pragma unroll
            for (int w2 = 0; w2 < WARPS_B; w2++) s += s_red[w2][lane];
            g_pScores[blockIdx.x][lane] = s;
        }
        if (lane == 0) {
            float s = 0.f;
            #pragma unroll
            for (int w2 = 0; w2 < WARPS_B; w2++) s += s_aux[w2];
            g_pAux[blockIdx.x] = s;
        }
        __threadfence();   // writers themselves fence (airtight ordering)
    }
    __syncthreads();
    if (tid == 0) s_last = atomicAdd(&g_sync, 1u);
    __syncthreads();
    if (s_last != NBLOCKS_B - 1) return;

    // ================= last-block finalize (wk_c work) ======================
    __threadfence();
    __shared__ float s_mask[BB * EE];
    __shared__ float s_auxw[WARPS_B];

    // aux: 4 partials per thread
    float av = g_pAux[tid] + g_pAux[tid + 256] + g_pAux[tid + 512] + g_pAux[tid + 768];
    #pragma unroll
    for (int off = 16; off > 0; off >>= 1) av += __shfl_xor_sync(0xFFFFFFFFu, av, off);
    if (lane == 0) s_auxw[warp] = av;

    // scores: 4 threads per batch, 4 partial-blocks each
    int b   = tid >> 2;            // 0..63
    int sub = tid & 3;
    const float4* ps = (const float4*)g_pScores;   // [1024][2] float4
    float4 lo = make_float4(0.f, 0.f, 0.f, 0.f);
    float4 hi = make_float4(0.f, 0.f, 0.f, 0.f);
    #pragma unroll
    for (int k = 0; k < 4; k++) {
        int idx = (b * BLOCKS_PER_BATCH + sub * 4 + k) * 2;
        float4 l = ps[idx], h = ps[idx + 1];
        lo.x += l.x; lo.y += l.y; lo.z += l.z; lo.w += l.w;
        hi.x += h.x; hi.y += h.y; hi.z += h.z; hi.w += h.w;
    }
    #pragma unroll
    for (int off = 2; off > 0; off >>= 1) {
        lo.x += __shfl_xor_sync(0xFFFFFFFFu, lo.x, off);
        lo.y += __shfl_xor_sync(0xFFFFFFFFu, lo.y, off);
        lo.z += __shfl_xor_sync(0xFFFFFFFFu, lo.z, off);
        lo.w += __shfl_xor_sync(0xFFFFFFFFu, lo.w, off);
        hi.x += __shfl_xor_sync(0xFFFFFFFFu, hi.x, off);
        hi.y += __shfl_xor_sync(0xFFFFFFFFu, hi.y, off);
        hi.z += __shfl_xor_sync(0xFFFFFFFFu, hi.z, off);
        hi.w += __shfl_xor_sync(0xFFFFFFFFu, hi.w, off);
    }

    if (sub == 0) {
        float sc[EE] = {lo.x, lo.y, lo.z, lo.w, hi.x, hi.y, hi.z, hi.w};
        // top-2, ties -> lowest index first (jax.lax.top_k semantics)
        int i1 = 0; float v1 = sc[0];
        #pragma unroll
        for (int e = 1; e < EE; e++) if (sc[e] > v1) { v1 = sc[e]; i1 = e; }
        int i2 = -1; float v2 = -3.402823466e38f;
        #pragma unroll
        for (int e = 0; e < EE; e++)
            if (e != i1 && sc[e] > v2) { v2 = sc[e]; i2 = e; }
        #pragma unroll
        for (int e = 0; e < EE; e++) {
            float mv = (e == i1 || e == i2) ? 1.0f : 0.0f;
            s_mask[b * EE + e]   = mv;
            g_mask2d[b * EE + e] = mv;
        }
        out[IDX_OFF + b * KTOP + 0] = (float)i1;
        out[IDX_OFF + b * KTOP + 1] = (float)i2;
    }
    __syncthreads();

    if (warp == 0) {
        float aw = (lane < WARPS_B) ? s_auxw[lane] : 0.f;
        #pragma unroll
        for (int off = 16; off > 0; off >>= 1) aw += __shfl_xor_sync(0xFFFFFFFFu, aw, off);
        float aux = aw / (float)(BB * SS * EE);

        float t = 0.f;
        if (lane < EE) {
            float cnt = 0.f;
            #pragma unroll 8
            for (int bb = 0; bb < BB; bb++) cnt += s_mask[bb * EE + lane];
            const float ideal = 1.0f / (float)EE;
            t = ideal * (__logf(ideal) - __logf(cnt / (float)BB));
        }
        #pragma unroll
        for (int off = 4; off > 0; off >>= 1) t += __shfl_xor_sync(0xFFFFFFFFu, t, off);
        if (lane == 0) {
            out[LOSS_OFF] = 1e-3f * (t / (float)EE) + 1e-3f * aux;
            g_sync = 0;   // reset for next graph replay
        }
    }
}

// ---------------- Kernel D: broadcast mask2d -> mask [B,S,E] ----------------
__global__ void __launch_bounds__(256) wk_d(float* __restrict__ out) {
    int i = blockIdx.x * blockDim.x + threadIdx.x;  // float4 index
    int g = i * 4;
    if (g >= MASK_ELEMS) return;
    int b  = g >> 13;        // / (S*E) = /8192
    int e0 = g & 7;          // 0 or 4 -> float4-aligned
    float4 v = *(const float4*)(g_mask2d + b * EE + e0);
    *(float4*)(out + g) = v;
}

// ---------------- launch ----------------------------------------------------
extern "C" void kernel_launch(void* const* d_in, const int* in_sizes, int n_in,
                              void* d_out, int out_size) {
    const float* x   = (const float*)d_in[0];
    const float* Wq  = (const float*)d_in[1];
    const float* bq  = (const float*)d_in[2];
    const float* key = (const float*)d_in[3];
    float* out = (float*)d_out;

    wk_w<<<dim3(EE, 8), 256>>>(Wq, bq, key);
    wk_b<<<NBLOCKS_B, BTHREADS>>>(x, out);
    wk_d<<<(MASK_ELEMS / 4 + 255) / 256, 256>>>(out);
}

// round 7
// speedup vs baseline: 1.3055x; 1.3055x over previous
#include <cuda_runtime.h>
#include <math.h>

#define BB 64
#define SS 1024
#define DD 1024
#define EE 8
#define KTOP 2

#define OS 32                                  // o-chunks for W2 partials

// wk_b geometry: warp = 8 d-lanes x 4 octets, 4 tokens/lane, 16 tokens/warp
#define BTHREADS 256
#define WARPS_B (BTHREADS / 32)                // 8
#define TOK_PER_WARP 16
#define BLK_TOK (WARPS_B * TOK_PER_WARP)       // 128
#define NBLOCKS_B (BB * SS / BLK_TOK)          // 512
#define BLOCKS_PER_BATCH (SS / BLK_TOK)        // 8

#define MASK_ELEMS (BB * SS * EE)   // 524288
#define IDX_OFF    MASK_ELEMS
#define LOSS_OFF   (MASK_ELEMS + BB * KTOP)

// ---------------- scratch (device globals: no allocation allowed) ----------
__device__ float g_W2part[OS][EE][DD];       // 1 MB
__device__ float g_W2[EE * DD];              // 32 KB
__device__ float g_b2[EE];
__device__ float g_pScores[NBLOCKS_B][EE];   // per-block partial softmax sums
__device__ float g_pAux[NBLOCKS_B];          // per-block partial aux sums
__device__ float g_mask2d[BB * EE];
__device__ unsigned int g_sync;              // last-block counter (self-resetting)

// ------------- Kernel A: all-expert partial W2 over an o-chunk -------------
// grid 32 (o-chunks of 32), 256 thr; thread owns float4 of d; Wq read ONCE.
__global__ void __launch_bounds__(256) wk_a(const float* __restrict__ Wq,
                                            const float* __restrict__ key) {
    __shared__ float s_key[EE][OS];
    const int oc = blockIdx.x;
    const int tid = threadIdx.x;
    if (tid < EE * OS) {
        int e = tid >> 5, o = tid & 31;
        s_key[e][o] = key[e * DD + oc * OS + o];
    }
    __syncthreads();

    const int d = tid * 4;
    float4 acc[EE];
    #pragma unroll
    for (int e = 0; e < EE; e++) acc[e] = make_float4(0.f, 0.f, 0.f, 0.f);

    const float* wq = Wq + (size_t)(oc * OS) * DD + d;
    #pragma unroll 4
    for (int o = 0; o < OS; o++) {
        float4 w = *(const float4*)(wq + (size_t)o * DD);
        #pragma unroll
        for (int e = 0; e < EE; e++) {
            float k = s_key[e][o];
            acc[e].x = fmaf(k, w.x, acc[e].x);
            acc[e].y = fmaf(k, w.y, acc[e].y);
            acc[e].z = fmaf(k, w.z, acc[e].z);
            acc[e].w = fmaf(k, w.w, acc[e].w);
        }
    }
    #pragma unroll
    for (int e = 0; e < EE; e++)
        *(float4*)&g_W2part[oc][e][d] = acc[e];
}

// ------------- Kernel A2: reduce partials -> W2, plus b2 --------------------
// grid 8 (e), 256 thr; thread sums 32 partial float4s (unrolled, high MLP).
__global__ void __launch_bounds__(256) wk_a2(const float* __restrict__ bq,
                                             const float* __restrict__ key) {
    __shared__ float s_part[WARPS_B];
    const int e = blockIdx.x;
    const int tid = threadIdx.x;
    const int d = tid * 4;
    float4 s = make_float4(0.f, 0.f, 0.f, 0.f);
    #pragma unroll 8
    for (int oc = 0; oc < OS; oc++) {
        float4 p = *(const float4*)&g_W2part[oc][e][d];
        s.x += p.x; s.y += p.y; s.z += p.z; s.w += p.w;
    }
    *(float4*)&g_W2[e * DD + d] = s;

    float4 bv = *(const float4*)(bq + d);
    float4 kv = *(const float4*)(key + e * DD + d);
    float p = bv.x * kv.x + bv.y * kv.y + bv.z * kv.z + bv.w * kv.w;
    #pragma unroll
    for (int off = 16; off > 0; off >>= 1) p += __shfl_xor_sync(0xFFFFFFFFu, p, off);
    int warp = tid >> 5, lane = tid & 31;
    if (lane == 0) s_part[warp] = p;
    __syncthreads();
    if (tid == 0) {
        float b2 = 0.f;
        #pragma unroll
        for (int w = 0; w < WARPS_B; w++) b2 += s_part[w];
        g_b2[e] = b2;
    }
}

// ---------------- Kernel B: fused main pass + last-block finalize -----------
__global__ void __launch_bounds__(BTHREADS, 3) wk_b(const float* __restrict__ x,
                                                    float* __restrict__ out) {
    __shared__ float4 s_w2[EE * 256];            // 32 KB, [e][j]
    __shared__ float  s_b2[EE];
    __shared__ float  s_red[WARPS_B][EE];
    __shared__ float  s_aux[WARPS_B];
    __shared__ unsigned int s_last;

    const int tid = threadIdx.x;
    const float4* w2g = (const float4*)g_W2;
    #pragma unroll
    for (int i = 0; i < 8; i++) s_w2[tid + i * 256] = w2g[tid + i * 256];
    if (tid < EE) s_b2[tid] = g_b2[tid];
    __syncthreads();

    const int warp = tid >> 5, lane = tid & 31;
    const int oct  = lane >> 3;
    const int c    = lane & 7;
    const int tokBase = blockIdx.x * BLK_TOK + warp * TOK_PER_WARP;

    const float4* xg = (const float4*)x;
    size_t base[4];
    #pragma unroll
    for (int t = 0; t < 4; t++)
        base[t] = (size_t)(tokBase + t * 4 + oct) * 256 + c;

    float acc[4][EE];
    #pragma unroll
    for (int t = 0; t < 4; t++)
        #pragma unroll
        for (int e = 0; e < EE; e++) acc[t][e] = 0.f;

    #pragma unroll 2
    for (int i = 0; i < 32; i++) {
        float4 xv[4];
        #pragma unroll
        for (int t = 0; t < 4; t++) xv[t] = xg[base[t] + i * 8];
        #pragma unroll
        for (int e = 0; e < EE; e++) {
            float4 wv = s_w2[e * 256 + i * 8 + c];
            #pragma unroll
            for (int t = 0; t < 4; t++) {
                acc[t][e] = fmaf(xv[t].x, wv.x, acc[t][e]);
                acc[t][e] = fmaf(xv[t].y, wv.y, acc[t][e]);
                acc[t][e] = fmaf(xv[t].z, wv.z, acc[t][e]);
                acc[t][e] = fmaf(xv[t].w, wv.w, acc[t][e]);
            }
        }
    }

    // octet reduce: all 8 lanes of the octet end with the full dots
    #pragma unroll
    for (int t = 0; t < 4; t++)
        #pragma unroll
        for (int e = 0; e < EE; e++) {
            float v = acc[t][e];
            v += __shfl_xor_sync(0xFFFFFFFFu, v, 4);
            v += __shfl_xor_sync(0xFFFFFFFFu, v, 2);
            v += __shfl_xor_sync(0xFFFFFFFFu, v, 1);
            acc[t][e] = v;
        }

    // per-token softmax (redundant across octet lanes; only c==0 contributes)
    const float scale = 0.03125f;
    float b2r[EE];
    #pragma unroll
    for (int e = 0; e < EE; e++) b2r[e] = s_b2[e];

    float scoreAcc[EE];
    #pragma unroll
    for (int e = 0; e < EE; e++) scoreAcc[e] = 0.f;
    float auxAcc = 0.f;
    const float contrib = (c == 0) ? 1.0f : 0.0f;

    #pragma unroll
    for (int t = 0; t < 4; t++) {
        float z[EE];
        float m = -3.402823466e38f;
        #pragma unroll
        for (int e = 0; e < EE; e++) { z[e] = acc[t][e] + b2r[e]; m = fmaxf(m, z[e]); }
        float ex[EE];
        float denom = 0.f;
        #pragma unroll
        for (int e = 0; e < EE; e++) { ex[e] = __expf((z[e] - m) * scale); denom += ex[e]; }
        float rdenom = __frcp_rn(denom);
        #pragma unroll
        for (int e = 0; e < EE; e++) {
            float w = ex[e] * rdenom;
            scoreAcc[e] += contrib * w;
            auxAcc      += contrib * w * __logf(w + 1e-9f);
        }
    }

    // block reduce
    #pragma unroll
    for (int e = 0; e < EE; e++) {
        float v = scoreAcc[e];
        v += __shfl_xor_sync(0xFFFFFFFFu, v, 16);
        v += __shfl_xor_sync(0xFFFFFFFFu, v, 8);
        v += __shfl_xor_sync(0xFFFFFFFFu, v, 4);
        v += __shfl_xor_sync(0xFFFFFFFFu, v, 2);
        v += __shfl_xor_sync(0xFFFFFFFFu, v, 1);
        if (lane == 0) s_red[warp][e] = v;
    }
    float a = auxAcc;
    #pragma unroll
    for (int off = 16; off > 0; off >>= 1) a += __shfl_xor_sync(0xFFFFFFFFu, a, off);
    if (lane == 0) s_aux[warp] = a;
    __syncthreads();

    if (warp == 0) {
        if (lane < EE) {
            float s = 0.f;
            #pragma unroll
            for (int w2 = 0; w2 < WARPS_B; w2++) s += s_red[w2][lane];
            g_pScores[blockIdx.x][lane] = s;
        }
        if (lane == 0) {
            float s = 0.f;
            #pragma unroll
            for (int w2 = 0; w2 < WARPS_B; w2++) s += s_aux[w2];
            g_pAux[blockIdx.x] = s;
        }
        __threadfence();
    }
    __syncthreads();
    if (tid == 0) s_last = atomicAdd(&g_sync, 1u);
    __syncthreads();
    if (s_last != NBLOCKS_B - 1) return;

    // ================= last-block finalize ==================================
    __threadfence();
    __shared__ float s_mask[BB * EE];
    __shared__ float s_auxw[WARPS_B];

    // aux: 2 partials per thread (NBLOCKS_B = 512)
    float av = g_pAux[tid] + g_pAux[tid + 256];
    #pragma unroll
    for (int off = 16; off > 0; off >>= 1) av += __shfl_xor_sync(0xFFFFFFFFu, av, off);
    if (lane == 0) s_auxw[warp] = av;

    // scores: 4 threads per batch, 2 partial-blocks each (BLOCKS_PER_BATCH=8)
    int b   = tid >> 2;            // 0..63
    int sub = tid & 3;
    const float4* ps = (const float4*)g_pScores;   // [512][2] float4
    float4 lo = make_float4(0.f, 0.f, 0.f, 0.f);
    float4 hi = make_float4(0.f, 0.f, 0.f, 0.f);
    #pragma unroll
    for (int k = 0; k < 2; k++) {
        int idx = (b * BLOCKS_PER_BATCH + sub * 2 + k) * 2;
        float4 l = ps[idx], h = ps[idx + 1];
        lo.x += l.x; lo.y += l.y; lo.z += l.z; lo.w += l.w;
        hi.x += h.x; hi.y += h.y; hi.z += h.z; hi.w += h.w;
    }
    #pragma unroll
    for (int off = 2; off > 0; off >>= 1) {
        lo.x += __shfl_xor_sync(0xFFFFFFFFu, lo.x, off);
        lo.y += __shfl_xor_sync(0xFFFFFFFFu, lo.y, off);
        lo.z += __shfl_xor_sync(0xFFFFFFFFu, lo.z, off);
        lo.w += __shfl_xor_sync(0xFFFFFFFFu, lo.w, off);
        hi.x += __shfl_xor_sync(0xFFFFFFFFu, hi.x, off);
        hi.y += __shfl_xor_sync(0xFFFFFFFFu, hi.y, off);
        hi.z += __shfl_xor_sync(0xFFFFFFFFu, hi.z, off);
        hi.w += __shfl_xor_sync(0xFFFFFFFFu, hi.w, off);
    }

    if (sub == 0) {
        float sc[EE] = {lo.x, lo.y, lo.z, lo.w, hi.x, hi.y, hi.z, hi.w};
        // top-2, ties -> lowest index first (jax.lax.top_k semantics)
        int i1 = 0; float v1 = sc[0];
        #pragma unroll
        for (int e = 1; e < EE; e++) if (sc[e] > v1) { v1 = sc[e]; i1 = e; }
        int i2 = -1; float v2 = -3.402823466e38f;
        #pragma unroll
        for (int e = 0; e < EE; e++)
            if (e != i1 && sc[e] > v2) { v2 = sc[e]; i2 = e; }
        #pragma unroll
        for (int e = 0; e < EE; e++) {
            float mv = (e == i1 || e == i2) ? 1.0f : 0.0f;
            s_mask[b * EE + e]   = mv;
            g_mask2d[b * EE + e] = mv;
        }
        out[IDX_OFF + b * KTOP + 0] = (float)i1;
        out[IDX_OFF + b * KTOP + 1] = (float)i2;
    }
    __syncthreads();

    if (warp == 0) {
        float aw = (lane < WARPS_B) ? s_auxw[lane] : 0.f;
        #pragma unroll
        for (int off = 16; off > 0; off >>= 1) aw += __shfl_xor_sync(0xFFFFFFFFu, aw, off);
        float aux = aw / (float)(BB * SS * EE);

        float t = 0.f;
        if (lane < EE) {
            float cnt = 0.f;
            #pragma unroll 8
            for (int bb = 0; bb < BB; bb++) cnt += s_mask[bb * EE + lane];
            const float ideal = 1.0f / (float)EE;
            t = ideal * (__logf(ideal) - __logf(cnt / (float)BB));
        }
        #pragma unroll
        for (int off = 4; off > 0; off >>= 1) t += __shfl_xor_sync(0xFFFFFFFFu, t, off);
        if (lane == 0) {
            out[LOSS_OFF] = 1e-3f * (t / (float)EE) + 1e-3f * aux;
            g_sync = 0;   // reset for next graph replay
        }
    }
}

// ---------------- Kernel D: broadcast mask2d -> mask [B,S,E] ----------------
__global__ void __launch_bounds__(256) wk_d(float* __restrict__ out) {
    int i = blockIdx.x * blockDim.x + threadIdx.x;  // float4 index
    int g = i * 4;
    if (g >= MASK_ELEMS) return;
    int b  = g >> 13;        // / (S*E) = /8192
    int e0 = g & 7;          // 0 or 4 -> float4-aligned
    float4 v = *(const float4*)(g_mask2d + b * EE + e0);
    *(float4*)(out + g) = v;
}

// ---------------- launch ----------------------------------------------------
extern "C" void kernel_launch(void* const* d_in, const int* in_sizes, int n_in,
                              void* d_out, int out_size) {
    const float* x   = (const float*)d_in[0];
    const float* Wq  = (const float*)d_in[1];
    const float* bq  = (const float*)d_in[2];
    const float* key = (const float*)d_in[3];
    float* out = (float*)d_out;

    wk_a<<<OS, 256>>>(Wq, key);
    wk_a2<<<EE, 256>>>(bq, key);
    wk_b<<<NBLOCKS_B, BTHREADS>>>(x, out);
    wk_d<<<(MASK_ELEMS / 4 + 255) / 256, 256>>>(out);
}

// round 8
// speedup vs baseline: 1.3081x; 1.0020x over previous
#include <cuda_runtime.h>
#include <math.h>

#define BB 64
#define SS 1024
#define DD 1024
#define EE 8
#define KTOP 2

#define OS 32                                  // o-chunks for W2 partials

// wk_b geometry (R5 proven): warp = 4 token-octets, 2 tokens/lane, 8 tok/warp
#define BTHREADS 256
#define WARPS_B (BTHREADS / 32)                // 8
#define TOK_PER_WARP 8
#define BLK_TOK (WARPS_B * TOK_PER_WARP)       // 64
#define NBLOCKS_B (BB * SS / BLK_TOK)          // 1024
#define BLOCKS_PER_BATCH (SS / BLK_TOK)        // 16

#define MASK_ELEMS (BB * SS * EE)   // 524288
#define IDX_OFF    MASK_ELEMS
#define LOSS_OFF   (MASK_ELEMS + BB * KTOP)

// ---------------- scratch (device globals: no allocation allowed) ----------
__device__ float g_W2part[OS][EE][DD];       // 1 MB
__device__ float g_W2[EE * DD];              // 32 KB
__device__ float g_b2[EE];
__device__ float g_pScores[NBLOCKS_B][EE];   // per-block partial softmax sums
__device__ float g_pAux[NBLOCKS_B];          // per-block partial aux sums
__device__ float g_mask2d[BB * EE];

// ------------- Kernel A: all-expert partial W2 over an o-chunk -------------
// grid 32, 256 thr; thread owns float4 of d; Wq read ONCE (4 MB total).
__global__ void __launch_bounds__(256) wk_a(const float* __restrict__ Wq,
                                            const float* __restrict__ key) {
    __shared__ float s_key[EE][OS];
    const int oc = blockIdx.x;
    const int tid = threadIdx.x;
    if (tid < EE * OS) {
        int e = tid >> 5, o = tid & 31;
        s_key[e][o] = key[e * DD + oc * OS + o];
    }
    __syncthreads();

    const int d = tid * 4;
    float4 acc[EE];
    #pragma unroll
    for (int e = 0; e < EE; e++) acc[e] = make_float4(0.f, 0.f, 0.f, 0.f);

    const float* wq = Wq + (size_t)(oc * OS) * DD + d;
    #pragma unroll 4
    for (int o = 0; o < OS; o++) {
        float4 w = *(const float4*)(wq + (size_t)o * DD);
        #pragma unroll
        for (int e = 0; e < EE; e++) {
            float k = s_key[e][o];
            acc[e].x = fmaf(k, w.x, acc[e].x);
            acc[e].y = fmaf(k, w.y, acc[e].y);
            acc[e].z = fmaf(k, w.z, acc[e].z);
            acc[e].w = fmaf(k, w.w, acc[e].w);
        }
    }
    #pragma unroll
    for (int e = 0; e < EE; e++)
        *(float4*)&g_W2part[oc][e][d] = acc[e];
}

// ------------- Kernel A2: reduce partials -> W2, plus b2 --------------------
__global__ void __launch_bounds__(256) wk_a2(const float* __restrict__ bq,
                                             const float* __restrict__ key) {
    __shared__ float s_part[WARPS_B];
    const int e = blockIdx.x;
    const int tid = threadIdx.x;
    const int d = tid * 4;
    float4 s = make_float4(0.f, 0.f, 0.f, 0.f);
    #pragma unroll 8
    for (int oc = 0; oc < OS; oc++) {
        float4 p = *(const float4*)&g_W2part[oc][e][d];
        s.x += p.x; s.y += p.y; s.z += p.z; s.w += p.w;
    }
    *(float4*)&g_W2[e * DD + d] = s;

    float4 bv = *(const float4*)(bq + d);
    float4 kv = *(const float4*)(key + e * DD + d);
    float p = bv.x * kv.x + bv.y * kv.y + bv.z * kv.z + bv.w * kv.w;
    #pragma unroll
    for (int off = 16; off > 0; off >>= 1) p += __shfl_xor_sync(0xFFFFFFFFu, p, off);
    int warp = tid >> 5, lane = tid & 31;
    if (lane == 0) s_part[warp] = p;
    __syncthreads();
    if (tid == 0) {
        float b2 = 0.f;
        #pragma unroll
        for (int w = 0; w < WARPS_B; w++) b2 += s_part[w];
        g_b2[e] = b2;
    }
}

// ---------------- Kernel B: main fused pass (R5 proven config) --------------
__global__ void __launch_bounds__(BTHREADS, 5) wk_b(const float* __restrict__ x) {
    __shared__ float4 s_w2[EE * 256];            // 32 KB, [e][j]
    __shared__ float  s_b2[EE];
    __shared__ float  s_red[WARPS_B][EE];
    __shared__ float  s_aux[WARPS_B];

    const int tid = threadIdx.x;
    const float4* w2g = (const float4*)g_W2;
    #pragma unroll
    for (int i = 0; i < 8; i++) s_w2[tid + i * 256] = w2g[tid + i * 256];
    if (tid < EE) s_b2[tid] = g_b2[tid];
    __syncthreads();

    const int warp = tid >> 5, lane = tid & 31;
    const int oct  = lane >> 3;
    const int c    = lane & 7;
    const int tokBase = blockIdx.x * BLK_TOK + warp * TOK_PER_WARP;

    const float4* xg = (const float4*)x;
    const size_t base0 = (size_t)(tokBase + oct)     * 256 + c;
    const size_t base1 = (size_t)(tokBase + 4 + oct) * 256 + c;

    float acc[2][EE];
    #pragma unroll
    for (int t = 0; t < 2; t++)
        #pragma unroll
        for (int e = 0; e < EE; e++) acc[t][e] = 0.f;

    #pragma unroll 4
    for (int i = 0; i < 32; i++) {
        float4 xv0 = xg[base0 + i * 8];
        float4 xv1 = xg[base1 + i * 8];
        #pragma unroll
        for (int e = 0; e < EE; e++) {
            float4 wv = s_w2[e * 256 + i * 8 + c];
            acc[0][e] = fmaf(xv0.x, wv.x, acc[0][e]);
            acc[0][e] = fmaf(xv0.y, wv.y, acc[0][e]);
            acc[0][e] = fmaf(xv0.z, wv.z, acc[0][e]);
            acc[0][e] = fmaf(xv0.w, wv.w, acc[0][e]);
            acc[1][e] = fmaf(xv1.x, wv.x, acc[1][e]);
            acc[1][e] = fmaf(xv1.y, wv.y, acc[1][e]);
            acc[1][e] = fmaf(xv1.z, wv.z, acc[1][e]);
            acc[1][e] = fmaf(xv1.w, wv.w, acc[1][e]);
        }
    }

    // octet reduce
    #pragma unroll
    for (int t = 0; t < 2; t++)
        #pragma unroll
        for (int e = 0; e < EE; e++) {
            float v = acc[t][e];
            v += __shfl_xor_sync(0xFFFFFFFFu, v, 4);
            v += __shfl_xor_sync(0xFFFFFFFFu, v, 2);
            v += __shfl_xor_sync(0xFFFFFFFFu, v, 1);
            acc[t][e] = v;
        }

    // per-token softmax (redundant across octet lanes; only c==0 contributes)
    const float scale = 0.03125f;
    float b2r[EE];
    #pragma unroll
    for (int e = 0; e < EE; e++) b2r[e] = s_b2[e];

    float scoreAcc[EE];
    #pragma unroll
    for (int e = 0; e < EE; e++) scoreAcc[e] = 0.f;
    float auxAcc = 0.f;
    const float contrib = (c == 0) ? 1.0f : 0.0f;

    #pragma unroll
    for (int t = 0; t < 2; t++) {
        float z[EE];
        float m = -3.402823466e38f;
        #pragma unroll
        for (int e = 0; e < EE; e++) { z[e] = acc[t][e] + b2r[e]; m = fmaxf(m, z[e]); }
        float ex[EE];
        float denom = 0.f;
        #pragma unroll
        for (int e = 0; e < EE; e++) { ex[e] = __expf((z[e] - m) * scale); denom += ex[e]; }
        float rdenom = __frcp_rn(denom);
        #pragma unroll
        for (int e = 0; e < EE; e++) {
            float w = ex[e] * rdenom;
            scoreAcc[e] += contrib * w;
            auxAcc      += contrib * w * __logf(w + 1e-9f);
        }
    }

    // block reduce
    #pragma unroll
    for (int e = 0; e < EE; e++) {
        float v = scoreAcc[e];
        v += __shfl_xor_sync(0xFFFFFFFFu, v, 16);
        v += __shfl_xor_sync(0xFFFFFFFFu, v, 8);
        v += __shfl_xor_sync(0xFFFFFFFFu, v, 4);
        v += __shfl_xor_sync(0xFFFFFFFFu, v, 2);
        v += __shfl_xor_sync(0xFFFFFFFFu, v, 1);
        if (lane == 0) s_red[warp][e] = v;
    }
    float a = auxAcc;
    #pragma unroll
    for (int off = 16; off > 0; off >>= 1) a += __shfl_xor_sync(0xFFFFFFFFu, a, off);
    if (lane == 0) s_aux[warp] = a;
    __syncthreads();

    if (warp == 0) {
        if (lane < EE) {
            float s = 0.f;
            #pragma unroll
            for (int w2 = 0; w2 < WARPS_B; w2++) s += s_red[w2][lane];
            g_pScores[blockIdx.x][lane] = s;
        }
        if (lane == 0) {
            float s = 0.f;
            #pragma unroll
            for (int w2 = 0; w2 < WARPS_B; w2++) s += s_aux[w2];
            g_pAux[blockIdx.x] = s;
        }
    }
}

// ---------------- Kernel C: top-k, mask2d, router loss (R5 proven) ----------
__global__ void __launch_bounds__(1024) wk_c(float* __restrict__ out) {
    __shared__ float s_mask[BB * EE];
    __shared__ float s_auxw[32];
    int tid  = threadIdx.x;
    int warp = tid >> 5, lane = tid & 31;

    // aux partial: one element per thread (NBLOCKS_B == 1024)
    float a = g_pAux[tid];
    #pragma unroll
    for (int off = 16; off > 0; off >>= 1) a += __shfl_xor_sync(0xFFFFFFFFu, a, off);
    if (lane == 0) s_auxw[warp] = a;

    // scores: half-warp per batch (64 batches, 32 warps)
    int b   = tid >> 4;            // 0..63
    int sub = tid & 15;
    const float4* ps = (const float4*)g_pScores;   // [1024][2] float4
    float4 lo = ps[(b * BLOCKS_PER_BATCH + sub) * 2 + 0];
    float4 hi = ps[(b * BLOCKS_PER_BATCH + sub) * 2 + 1];
    #pragma unroll
    for (int off = 8; off > 0; off >>= 1) {
        lo.x += __shfl_xor_sync(0xFFFFFFFFu, lo.x, off);
        lo.y += __shfl_xor_sync(0xFFFFFFFFu, lo.y, off);
        lo.z += __shfl_xor_sync(0xFFFFFFFFu, lo.z, off);
        lo.w += __shfl_xor_sync(0xFFFFFFFFu, lo.w, off);
        hi.x += __shfl_xor_sync(0xFFFFFFFFu, hi.x, off);
        hi.y += __shfl_xor_sync(0xFFFFFFFFu, hi.y, off);
        hi.z += __shfl_xor_sync(0xFFFFFFFFu, hi.z, off);
        hi.w += __shfl_xor_sync(0xFFFFFFFFu, hi.w, off);
    }

    if (sub == 0) {
        float sc[EE] = {lo.x, lo.y, lo.z, lo.w, hi.x, hi.y, hi.z, hi.w};
        // top-2, ties -> lowest index first (jax.lax.top_k semantics)
        int i1 = 0; float v1 = sc[0];
        #pragma unroll
        for (int e = 1; e < EE; e++) if (sc[e] > v1) { v1 = sc[e]; i1 = e; }
        int i2 = -1; float v2 = -3.402823466e38f;
        #pragma unroll
        for (int e = 0; e < EE; e++)
            if (e != i1 && sc[e] > v2) { v2 = sc[e]; i2 = e; }
        #pragma unroll
        for (int e = 0; e < EE; e++) {
            float mv = (e == i1 || e == i2) ? 1.0f : 0.0f;
            s_mask[b * EE + e]   = mv;
            g_mask2d[b * EE + e] = mv;
        }
        out[IDX_OFF + b * KTOP + 0] = (float)i1;
        out[IDX_OFF + b * KTOP + 1] = (float)i2;
    }
    __syncthreads();

    if (warp == 0) {
        float av = s_auxw[lane];
        #pragma unroll
        for (int off = 16; off > 0; off >>= 1) av += __shfl_xor_sync(0xFFFFFFFFu, av, off);
        float aux = av / (float)(BB * SS * EE);

        float t = 0.f;
        if (lane < EE) {
            float cnt = 0.f;
            #pragma unroll 8
            for (int bb = 0; bb < BB; bb++) cnt += s_mask[bb * EE + lane];
            const float ideal = 1.0f / (float)EE;
            t = ideal * (__logf(ideal) - __logf(cnt / (float)BB));
        }
        #pragma unroll
        for (int off = 4; off > 0; off >>= 1) t += __shfl_xor_sync(0xFFFFFFFFu, t, off);
        if (lane == 0)
            out[LOSS_OFF] = 1e-3f * (t / (float)EE) + 1e-3f * aux;
    }
}

// ---------------- Kernel D: broadcast mask2d -> mask [B,S,E] ----------------
// 128 blocks x 256 thr; each thread reads its batch row once (b constant
// across its 4-float4 span since 2048 is a multiple of 4) and fires 4
// independent STG.128 -> throughput-limited, not latency-limited.
__global__ void __launch_bounds__(256) wk_d(float* __restrict__ out) {
    int t = blockIdx.x * blockDim.x + threadIdx.x;   // 0..32767
    int b = t >> 9;                                  // 512 threads per batch
    const float4* m = (const float4*)(g_mask2d + b * EE);
    float4 lo = m[0];
    float4 hi = m[1];
    float4* o = (float4*)out + (size_t)t * 4;
    o[0] = lo; o[1] = hi; o[2] = lo; o[3] = hi;
}

// ---------------- launch ----------------------------------------------------
extern "C" void kernel_launch(void* const* d_in, const int* in_sizes, int n_in,
                              void* d_out, int out_size) {
    const float* x   = (const float*)d_in[0];
    const float* Wq  = (const float*)d_in[1];
    const float* bq  = (const float*)d_in[2];
    const float* key = (const float*)d_in[3];
    float* out = (float*)d_out;

    wk_a<<<OS, 256>>>(Wq, key);
    wk_a2<<<EE, 256>>>(bq, key);
    wk_b<<<NBLOCKS_B, BTHREADS>>>(x);
    wk_c<<<1, 1024>>>(out);
    wk_d<<<128, 256>>>(out);
}

// round 9
// speedup vs baseline: 1.4608x; 1.1167x over previous
#include <cuda_runtime.h>
#include <math.h>

#define BB 64
#define SS 1024
#define DD 1024
#define EE 8
#define KTOP 2

#define OSPLIT 32                 // o-split for W2 precompute (R5 proven)

// wk_b geometry (R5 proven): warp = 4 token-octets, 2 tokens/lane, 8 tok/warp
#define BTHREADS 256
#define WARPS_B (BTHREADS / 32)                // 8
#define TOK_PER_WARP 8
#define BLK_TOK (WARPS_B * TOK_PER_WARP)       // 64
#define NBLOCKS_B (BB * SS / BLK_TOK)          // 1024
#define BLOCKS_PER_BATCH (SS / BLK_TOK)        // 16

#define MASK_ELEMS (BB * SS * EE)   // 524288
#define IDX_OFF    MASK_ELEMS
#define LOSS_OFF   (MASK_ELEMS + BB * KTOP)

typedef unsigned long long u64;

// packed dual-FMA: d.lo = fma(a.lo,b.lo,c.lo), d.hi = fma(a.hi,b.hi,c.hi)
__device__ __forceinline__ u64 ffma2(u64 a, u64 b, u64 c) {
    u64 d;
    asm("fma.rn.f32x2 %0, %1, %2, %3;" : "=l"(d) : "l"(a), "l"(b), "l"(c));
    return d;
}
__device__ __forceinline__ float f2_sum(u64 v) {
    return __uint_as_float((unsigned)(v & 0xffffffffull)) +
           __uint_as_float((unsigned)(v >> 32));
}

// ---------------- scratch (device globals: no allocation allowed) ----------
__device__ float g_W2part[OSPLIT][EE][DD];   // 1 MB
__device__ float g_W2[EE * DD];              // 32 KB
__device__ float g_b2[EE];
__device__ float g_pScores[NBLOCKS_B][EE];   // per-block partial softmax sums
__device__ float g_pAux[NBLOCKS_B];          // per-block partial aux sums
__device__ float g_mask2d[BB * EE];

// ---------------- Kernel A: partial W2 = key_emb @ Wq (R5 proven) ----------
// grid (E, OSPLIT=32), block 256. thread handles 4 contiguous d's (float4).
__global__ void __launch_bounds__(256) wk_a(const float* __restrict__ Wq,
                                            const float* __restrict__ key) {
    int e  = blockIdx.x;
    int oc = blockIdx.y;
    int d  = threadIdx.x * 4;
    const float* wq = Wq + (size_t)(oc * 32) * DD + d;
    const float* ke = key + e * DD + oc * 32;
    float4 acc = make_float4(0.f, 0.f, 0.f, 0.f);
    #pragma unroll
    for (int o = 0; o < 32; o++) {
        float k  = __ldg(ke + o);
        float4 w = *(const float4*)(wq + (size_t)o * DD);
        acc.x += k * w.x; acc.y += k * w.y; acc.z += k * w.z; acc.w += k * w.w;
    }
    *(float4*)&g_W2part[oc][e][d] = acc;
}

// ------------- Kernel A2: reduce o-split partials -> W2, plus b2 (R5) ------
__global__ void __launch_bounds__(256) wk_a2(const float* __restrict__ bq,
                                             const float* __restrict__ key) {
    __shared__ float s_part[WARPS_B];
    int e = blockIdx.x;
    int tid = threadIdx.x;
    int d = tid * 4;
    float4 s = make_float4(0.f, 0.f, 0.f, 0.f);
    #pragma unroll
    for (int oc = 0; oc < OSPLIT; oc++) {
        float4 p = *(const float4*)&g_W2part[oc][e][d];
        s.x += p.x; s.y += p.y; s.z += p.z; s.w += p.w;
    }
    *(float4*)&g_W2[e * DD + d] = s;

    float4 bv = *(const float4*)(bq + d);
    float4 kv = *(const float4*)(key + e * DD + d);
    float p = bv.x * kv.x + bv.y * kv.y + bv.z * kv.z + bv.w * kv.w;
    #pragma unroll
    for (int off = 16; off > 0; off >>= 1) p += __shfl_xor_sync(0xFFFFFFFFu, p, off);
    int warp = tid >> 5, lane = tid & 31;
    if (lane == 0) s_part[warp] = p;
    __syncthreads();
    if (tid == 0) {
        float b2 = 0.f;
        #pragma unroll
        for (int w = 0; w < WARPS_B; w++) b2 += s_part[w];
        g_b2[e] = b2;
    }
}

// ---------------- Kernel B: main fused pass (R5 config + FFMA2) -------------
__global__ void __launch_bounds__(BTHREADS, 4) wk_b(const float* __restrict__ x) {
    __shared__ float4 s_w2[EE * 256];            // 32 KB, [e][j]
    __shared__ float  s_b2[EE];
    __shared__ float  s_red[WARPS_B][EE];
    __shared__ float  s_aux[WARPS_B];

    const int tid = threadIdx.x;
    const float4* w2g = (const float4*)g_W2;
    #pragma unroll
    for (int i = 0; i < 8; i++) s_w2[tid + i * 256] = w2g[tid + i * 256];
    if (tid < EE) s_b2[tid] = g_b2[tid];
    __syncthreads();

    const int warp = tid >> 5, lane = tid & 31;
    const int oct  = lane >> 3;
    const int c    = lane & 7;
    const int tokBase = blockIdx.x * BLK_TOK + warp * TOK_PER_WARP;

    const ulonglong2* xg = (const ulonglong2*)x;   // 16B granules, 2 f32 per u64
    const size_t base0 = (size_t)(tokBase + oct)     * 256 + c;
    const size_t base1 = (size_t)(tokBase + 4 + oct) * 256 + c;

    u64 acc2[2][EE];
    #pragma unroll
    for (int t = 0; t < 2; t++)
        #pragma unroll
        for (int e = 0; e < EE; e++) acc2[t][e] = 0ull;   // (0.0f, 0.0f)

    #pragma unroll 4
    for (int i = 0; i < 32; i++) {
        ulonglong2 xv0 = xg[base0 + i * 8];
        ulonglong2 xv1 = xg[base1 + i * 8];
        #pragma unroll
        for (int e = 0; e < EE; e++) {
            ulonglong2 wv = *(const ulonglong2*)&s_w2[e * 256 + i * 8 + c];
            acc2[0][e] = ffma2(xv0.x, wv.x, acc2[0][e]);
            acc2[0][e] = ffma2(xv0.y, wv.y, acc2[0][e]);
            acc2[1][e] = ffma2(xv1.x, wv.x, acc2[1][e]);
            acc2[1][e] = ffma2(xv1.y, wv.y, acc2[1][e]);
        }
    }

    float acc[2][EE];
    #pragma unroll
    for (int t = 0; t < 2; t++)
        #pragma unroll
        for (int e = 0; e < EE; e++) acc[t][e] = f2_sum(acc2[t][e]);

    // octet reduce: all 8 lanes of the octet end with the full dots
    #pragma unroll
    for (int t = 0; t < 2; t++)
        #pragma unroll
        for (int e = 0; e < EE; e++) {
            float v = acc[t][e];
            v += __shfl_xor_sync(0xFFFFFFFFu, v, 4);
            v += __shfl_xor_sync(0xFFFFFFFFu, v, 2);
            v += __shfl_xor_sync(0xFFFFFFFFu, v, 1);
            acc[t][e] = v;
        }

    // per-token softmax (redundant across octet lanes; only c==0 contributes)
    const float scale = 0.03125f;
    float b2r[EE];
    #pragma unroll
    for (int e = 0; e < EE; e++) b2r[e] = s_b2[e];

    float scoreAcc[EE];
    #pragma unroll
    for (int e = 0; e < EE; e++) scoreAcc[e] = 0.f;
    float auxAcc = 0.f;
    const float contrib = (c == 0) ? 1.0f : 0.0f;

    #pragma unroll
    for (int t = 0; t < 2; t++) {
        float z[EE];
        float m = -3.402823466e38f;
        #pragma unroll
        for (int e = 0; e < EE; e++) { z[e] = acc[t][e] + b2r[e]; m = fmaxf(m, z[e]); }
        float ex[EE];
        float denom = 0.f;
        #pragma unroll
        for (int e = 0; e < EE; e++) { ex[e] = __expf((z[e] - m) * scale); denom += ex[e]; }
        float rdenom = __frcp_rn(denom);
        #pragma unroll
        for (int e = 0; e < EE; e++) {
            float w = ex[e] * rdenom;
            scoreAcc[e] += contrib * w;
            auxAcc      += contrib * w * __logf(w + 1e-9f);
        }
    }

    // block reduce
    #pragma unroll
    for (int e = 0; e < EE; e++) {
        float v = scoreAcc[e];
        v += __shfl_xor_sync(0xFFFFFFFFu, v, 16);
        v += __shfl_xor_sync(0xFFFFFFFFu, v, 8);
        v += __shfl_xor_sync(0xFFFFFFFFu, v, 4);
        v += __shfl_xor_sync(0xFFFFFFFFu, v, 2);
        v += __shfl_xor_sync(0xFFFFFFFFu, v, 1);
        if (lane == 0) s_red[warp][e] = v;
    }
    float a = auxAcc;
    #pragma unroll
    for (int off = 16; off > 0; off >>= 1) a += __shfl_xor_sync(0xFFFFFFFFu, a, off);
    if (lane == 0) s_aux[warp] = a;
    __syncthreads();

    if (warp == 0) {
        if (lane < EE) {
            float s = 0.f;
            #pragma unroll
            for (int w2 = 0; w2 < WARPS_B; w2++) s += s_red[w2][lane];
            g_pScores[blockIdx.x][lane] = s;
        }
        if (lane == 0) {
            float s = 0.f;
            #pragma unroll
            for (int w2 = 0; w2 < WARPS_B; w2++) s += s_aux[w2];
            g_pAux[blockIdx.x] = s;
        }
    }
}

// ---------------- Kernel C: top-k, mask2d, router loss (R5 proven) ----------
__global__ void __launch_bounds__(1024) wk_c(float* __restrict__ out) {
    __shared__ float s_mask[BB * EE];
    __shared__ float s_auxw[32];
    int tid  = threadIdx.x;
    int warp = tid >> 5, lane = tid & 31;

    // aux partial: one element per thread (NBLOCKS_B == 1024)
    float a = g_pAux[tid];
    #pragma unroll
    for (int off = 16; off > 0; off >>= 1) a += __shfl_xor_sync(0xFFFFFFFFu, a, off);
    if (lane == 0) s_auxw[warp] = a;

    // scores: half-warp per batch (64 batches, 32 warps)
    int b   = tid >> 4;            // 0..63
    int sub = tid & 15;
    const float4* ps = (const float4*)g_pScores;   // [1024][2] float4
    float4 lo = ps[(b * BLOCKS_PER_BATCH + sub) * 2 + 0];
    float4 hi = ps[(b * BLOCKS_PER_BATCH + sub) * 2 + 1];
    #pragma unroll
    for (int off = 8; off > 0; off >>= 1) {
        lo.x += __shfl_xor_sync(0xFFFFFFFFu, lo.x, off);
        lo.y += __shfl_xor_sync(0xFFFFFFFFu, lo.y, off);
        lo.z += __shfl_xor_sync(0xFFFFFFFFu, lo.z, off);
        lo.w += __shfl_xor_sync(0xFFFFFFFFu, lo.w, off);
        hi.x += __shfl_xor_sync(0xFFFFFFFFu, hi.x, off);
        hi.y += __shfl_xor_sync(0xFFFFFFFFu, hi.y, off);
        hi.z += __shfl_xor_sync(0xFFFFFFFFu, hi.z, off);
        hi.w += __shfl_xor_sync(0xFFFFFFFFu, hi.w, off);
    }

    if (sub == 0) {
        float sc[EE] = {lo.x, lo.y, lo.z, lo.w, hi.x, hi.y, hi.z, hi.w};
        // top-2, ties -> lowest index first (jax.lax.top_k semantics)
        int i1 = 0; float v1 = sc[0];
        #pragma unroll
        for (int e = 1; e < EE; e++) if (sc[e] > v1) { v1 = sc[e]; i1 = e; }
        int i2 = -1; float v2 = -3.402823466e38f;
        #pragma unroll
        for (int e = 0; e < EE; e++)
            if (e != i1 && sc[e] > v2) { v2 = sc[e]; i2 = e; }
        #pragma unroll
        for (int e = 0; e < EE; e++) {
            float mv = (e == i1 || e == i2) ? 1.0f : 0.0f;
            s_mask[b * EE + e]   = mv;
            g_mask2d[b * EE + e] = mv;
        }
        out[IDX_OFF + b * KTOP + 0] = (float)i1;
        out[IDX_OFF + b * KTOP + 1] = (float)i2;
    }
    __syncthreads();

    if (warp == 0) {
        float av = s_auxw[lane];
        #pragma unroll
        for (int off = 16; off > 0; off >>= 1) av += __shfl_xor_sync(0xFFFFFFFFu, av, off);
        float aux = av / (float)(BB * SS * EE);

        float t = 0.f;
        if (lane < EE) {
            float cnt = 0.f;
            #pragma unroll 8
            for (int bb = 0; bb < BB; bb++) cnt += s_mask[bb * EE + lane];
            const float ideal = 1.0f / (float)EE;
            t = ideal * (__logf(ideal) - __logf(cnt / (float)BB));
        }
        #pragma unroll
        for (int off = 4; off > 0; off >>= 1) t += __shfl_xor_sync(0xFFFFFFFFu, t, off);
        if (lane == 0)
            out[LOSS_OFF] = 1e-3f * (t / (float)EE) + 1e-3f * aux;
    }
}

// ---------------- Kernel D: broadcast mask2d -> mask [B,S,E] ----------------
// Each thread reads its batch row once (b constant across its 4-float4 span)
// and fires 4 independent STG.128.
__global__ void __launch_bounds__(256) wk_d(float* __restrict__ out) {
    int t = blockIdx.x * blockDim.x + threadIdx.x;   // 0..32767
    int b = t >> 9;                                  // 512 threads per batch
    const float4* m = (const float4*)(g_mask2d + b * EE);
    float4 lo = m[0];
    float4 hi = m[1];
    float4* o = (float4*)out + (size_t)t * 4;
    o[0] = lo; o[1] = hi; o[2] = lo; o[3] = hi;
}

// ---------------- launch ----------------------------------------------------
extern "C" void kernel_launch(void* const* d_in, const int* in_sizes, int n_in,
                              void* d_out, int out_size) {
    const float* x   = (const float*)d_in[0];
    const float* Wq  = (const float*)d_in[1];
    const float* bq  = (const float*)d_in[2];
    const float* key = (const float*)d_in[3];
    float* out = (float*)d_out;

    wk_a<<<dim3(EE, OSPLIT), 256>>>(Wq, key);
    wk_a2<<<EE, 256>>>(bq, key);
    wk_b<<<NBLOCKS_B, BTHREADS>>>(x);
    wk_c<<<1, 1024>>>(out);
    wk_d<<<128, 256>>>(out);
}